// round 14
// baseline (speedup 1.0000x reference)
#include <cuda_runtime.h>
#include <cuda_fp16.h>
#include <stdint.h>

// Problem constants
#define DIM   256
#define NC    1024
#define NPTS  65536
#define D4    (DIM/4)

// ---- filter kernel geometry ----
#define ROWS_CTA 128
#define NCT      8          // code tiles of 128 (one B chunk each, full K)
#define THR      512        // 16 warps: wy=wid>>2 (M: 32 rows), wx=wid&3 (N: 32 codes)
#define TAU      2.5e-4f

// filter smem offsets
#define SM_WSQ   0                     // 4 KB
#define SM_ZSQ   4096                  // 512 B
#define SM_RED   4608                  // 8 KB
#define SM_A     13312                 // 128 r x 512 B (fp16 z, full K, swizzled) = 64 KB
#define SM_B     (SM_A + 65536)        // 2 bufs x 64 KB (128 codes x 256 k fp16)
#define SM_TOTAL (SM_B + 131072)       // 209920 B

// ---- resolver geometry: 8 code-slices x 32 rows/CTA, slot-stride loop ----
#define RBM    32
#define RBN    128
#define RSLICE 8
#define RSLOTW 128
#define RKC4   32
#define RTM    4
#define RTN    4
#define RSM_TOTAL (RBM * 256 * 4 + RBN * RKC4 * 16 + 256)

// Scratch (static device globals; no allocation)
__device__ int   g_idx[NPTS];
__device__ float g_wsq[NC];
__device__ float g_zsq[NPTS];
__device__ int   g_ambig_n;
__device__ int   g_ambig[NPTS];
__device__ float g_bestS[RSLICE][NPTS];
__device__ int   g_bidxS[RSLICE][NPTS];
__device__ __align__(16) unsigned short g_wf[NC * DIM];     // fp16(w)

// ---- PTX helpers (baseline ops only; no arch-'a' features) -----------------
static __device__ __forceinline__ uint32_t smem_u32(const void* p) {
    uint32_t a;
    asm("{ .reg .u64 t; cvta.to.shared.u64 t, %1; cvt.u32.u64 %0, t; }"
        : "=r"(a) : "l"(p));
    return a;
}
#define CP16(dst, src) \
    asm volatile("cp.async.cg.shared.global [%0], [%1], 16;" :: "r"(dst), "l"(src))
#define STS128(addr, v) \
    asm volatile("st.shared.v4.b32 [%0], {%1,%2,%3,%4};" \
                 :: "r"(addr), "r"((v).x), "r"((v).y), "r"((v).z), "r"((v).w))
#define LDSM4(r, addr) \
    asm volatile("ldmatrix.sync.aligned.m8n8.x4.shared.b16 {%0,%1,%2,%3}, [%4];" \
                 : "=r"((r)[0]), "=r"((r)[1]), "=r"((r)[2]), "=r"((r)[3]) : "r"(addr))
#define MMA16816F(d, a, b) \
    asm volatile("mma.sync.aligned.m16n8k16.row.col.f32.f16.f16.f32 " \
                 "{%0,%1,%2,%3}, {%4,%5,%6,%7}, {%8,%9}, {%0,%1,%2,%3};" \
                 : "+f"((d)[0]), "+f"((d)[1]), "+f"((d)[2]), "+f"((d)[3]) \
                 : "r"((a)[0]), "r"((a)[1]), "r"((a)[2]), "r"((a)[3]), \
                   "r"((b)[0]), "r"((b)[1]))
static __device__ __forceinline__ void fma2(unsigned long long& d,
                                            unsigned long long a,
                                            unsigned long long b) {
    asm("fma.rn.f32x2 %0, %1, %2, %0;" : "+l"(d) : "l"(a), "l"(b));
}
static __device__ __forceinline__ void unpack2(unsigned long long v,
                                               float& lo, float& hi) {
    asm("mov.b64 {%0, %1}, %2;" : "=f"(lo), "=f"(hi) : "l"(v));
}

// ---------------------------------------------------------------------------
// [0] reset worklist counter
// ---------------------------------------------------------------------------
__global__ void reset_kernel() { g_ambig_n = 0; }

// ---------------------------------------------------------------------------
// [1,2] convert w -> fp16 + exact fp32 |w|^2 (two half launches)
// ---------------------------------------------------------------------------
__global__ void conv_w_kernel(const float* __restrict__ w, int row_off) {
    int row  = row_off + ((blockIdx.x * blockDim.x + threadIdx.x) >> 5);
    int lane = threadIdx.x & 31;
    if (row >= NC) return;
    const float4* src = reinterpret_cast<const float4*>(w + (size_t)row * DIM);
    float4 a = src[lane * 2], b = src[lane * 2 + 1];
    float x[8] = {a.x, a.y, a.z, a.w, b.x, b.y, b.z, b.w};
    float s = 0.f;
    uint32_t pk[4];
#pragma unroll
    for (int j = 0; j < 4; j++) {
        s += x[2 * j] * x[2 * j] + x[2 * j + 1] * x[2 * j + 1];
        uint32_t lo = __half_as_ushort(__float2half_rn(x[2 * j]));
        uint32_t hi = __half_as_ushort(__float2half_rn(x[2 * j + 1]));
        pk[j] = lo | (hi << 16);
    }
    *reinterpret_cast<uint4*>(g_wf + (size_t)row * DIM + lane * 8) =
        make_uint4(pk[0], pk[1], pk[2], pk[3]);
#pragma unroll
    for (int t = 16; t >= 1; t >>= 1) s += __shfl_xor_sync(0xffffffffu, s, t);
    if (lane == 0) g_wsq[row] = s;
}

// ---------------------------------------------------------------------------
// Full-K B chunk stage into ring-2 buffer: 128 codes x 256 k fp16 (64 KB).
// Per thread: 8 CP16, base addresses loop-invariant, swizzle XOR per column.
// ---------------------------------------------------------------------------
static __device__ __forceinline__ void stage_B(uint32_t sb, int tid, int ct) {
    const int buf = ct & 1;
    const int r0  = tid >> 2;              // code row 0..127 (4 threads/row)
    const int q0  = (tid & 3) * 8;         // first of 8 16B-columns
    const uint32_t dstb = sb + SM_B + (uint32_t)(buf * 65536) + (uint32_t)(r0 * 512);
    const uint32_t sw   = (uint32_t)((r0 & 7) << 4);
    const unsigned short* src = g_wf + (size_t)(ct * 128 + r0) * DIM + q0 * 8;
#pragma unroll
    for (int j = 0; j < 8; j++)
        CP16(dstb + (((uint32_t)((q0 + j) * 16)) ^ sw), src + j * 8);
}

// lex insert of candidate (v,i) into best-2
static __device__ __forceinline__ void ins2(float v, int i, float& b1v, int& b1i,
                                            float& b2v, int& b2i) {
    if (v < b1v || (v == b1v && i < b1i)) { b2v = b1v; b2i = b1i; b1v = v; b1i = i; }
    else if (v < b2v || (v == b2v && i < b2i)) { b2v = v; b2i = i; }
}

// load one k16 step's fragments into frag set SET (same buffer only).
// Row strides: A rows 512 B (mt step = 16 rows = 8192 B);
//              B rows 512 B (pr step = 16 rows = 8192 B).   <-- R13 bug fixed
#define LOADFRAGS(SET, ABASE, BBASE, K16) do {                      \
    uint32_t ak_ = ((uint32_t)((K16) * 32) + akh) ^ xl;             \
    uint32_t bk_ = ((uint32_t)((K16) * 32) + bkh) ^ xl;             \
    LDSM4(af[SET][0], (ABASE) + ak_);                               \
    LDSM4(af[SET][1], (ABASE) + 8192 + ak_);                        \
    LDSM4(bf[SET][0], (BBASE) + bk_);                               \
    LDSM4(bf[SET][1], (BBASE) + 8192 + bk_);                        \
} while (0)

// ---------------------------------------------------------------------------
// [3] HOT: single-product fp16 HMMA filter; fused z conversion + |z|^2.
// 8 full-K code-tile chunks, ring-2 B buffer, ONE barrier per chunk.
// ---------------------------------------------------------------------------
__global__ void __launch_bounds__(THR, 1)
mma_filter_kernel(const float4* __restrict__ z4) {
    extern __shared__ char smem[];
    const uint32_t sb = smem_u32(smem);
    const int tid  = threadIdx.x;
    const int lane = tid & 31;
    const int wid  = tid >> 5;
    const int wx   = wid & 3;        // N warp (32 codes)
    const int wy   = wid >> 2;       // M warp (32 rows)
    const int row0 = blockIdx.x * ROWS_CTA;

    float* swsq = reinterpret_cast<float*>(smem + SM_WSQ);
    float* szsq = reinterpret_cast<float*>(smem + SM_ZSQ);
    for (int i = tid; i < NC; i += THR) swsq[i] = g_wsq[i];

    // stage B chunk 0 first (cp.async overlaps the A conversion below)
    stage_B(sb, tid, 0);
    asm volatile("cp.async.commit_group;" ::: "memory");

    // convert z fp32 -> fp16 into swizzled smem A + per-row |z|^2
    {
        const int r  = tid >> 2;
        const int qq = tid & 3;
        const float4* zr = z4 + (size_t)(row0 + r) * D4 + qq * 16;
        const uint32_t abase = sb + SM_A + (uint32_t)(r * 512);
        const uint32_t sw    = (uint32_t)((r & 7) << 4);
        float s = 0.f;
#pragma unroll
        for (int j = 0; j < 8; j++) {
            float4 a = zr[2 * j], b = zr[2 * j + 1];
            float x[8] = {a.x, a.y, a.z, a.w, b.x, b.y, b.z, b.w};
            uint4 pk;
            uint32_t* pkp = &pk.x;
#pragma unroll
            for (int e = 0; e < 4; e++) {
                s += x[2 * e] * x[2 * e] + x[2 * e + 1] * x[2 * e + 1];
                uint32_t lo = __half_as_ushort(__float2half_rn(x[2 * e]));
                uint32_t hi = __half_as_ushort(__float2half_rn(x[2 * e + 1]));
                pkp[e] = lo | (hi << 16);
            }
            uint32_t off = abase + ((uint32_t)((qq * 8 + j) * 16) ^ sw);
            STS128(off, pk);
        }
        s += __shfl_xor_sync(0xffffffffu, s, 1);
        s += __shfl_xor_sync(0xffffffffu, s, 2);
        if (qq == 0) { szsq[r] = s; g_zsq[row0 + r] = s; }
    }

    float b1v[2][2], b2v[2][2];
    int   b1i[2][2], b2i[2][2];
#pragma unroll
    for (int mt = 0; mt < 2; mt++)
#pragma unroll
        for (int g = 0; g < 2; g++) {
            b1v[mt][g] = b2v[mt][g] = 3.4e38f;
            b1i[mt][g] = b2i[mt][g] = 0x7fffffff;
        }

    const uint32_t xl   = (uint32_t)((lane & 7) << 4);
    const uint32_t aRow = (uint32_t)((wy * 32 + (lane & 15)) * 512);
    const uint32_t akh  = (uint32_t)(((lane >> 4) & 1) * 16);
    const uint32_t bRow = (uint32_t)((wx * 32 + ((lane >> 4) << 3) + (lane & 7)) * 512);
    const uint32_t bkh  = (uint32_t)(((lane >> 3) & 1) * 16);

    uint32_t af[2][2][4];
    uint32_t bf[2][2][4];
    float Azr[2][2];
    bool azr_init = false;

    for (int ct = 0; ct < NCT; ct++) {
        asm volatile("cp.async.wait_group 0;" ::: "memory");
        __syncthreads();   // B chunk + (ct==0: A conversion, szsq) visible

        if (!azr_init) {
            azr_init = true;
#pragma unroll
            for (int mt = 0; mt < 2; mt++)
#pragma unroll
                for (int g = 0; g < 2; g++)
                    Azr[mt][g] = szsq[wy * 32 + mt * 16 + (lane >> 2) + g * 8];
        }

        // stage next chunk (overwrites buf of ct-1; its readers all finished
        // before the barrier above) — overlaps with the 16-k16 compute below
        if (ct + 1 < NCT) {
            stage_B(sb, tid, ct + 1);
            asm volatile("cp.async.commit_group;" ::: "memory");
        }

        const uint32_t ab = sb + SM_A + aRow;
        const uint32_t bb = sb + SM_B + (uint32_t)((ct & 1) * 65536) + bRow;

        float acc[2][4][4];
#pragma unroll
        for (int mt = 0; mt < 2; mt++)
#pragma unroll
            for (int nt = 0; nt < 4; nt++)
#pragma unroll
                for (int e = 0; e < 4; e++) acc[mt][nt][e] = 0.f;

        LOADFRAGS(0, ab, bb, 0);
#pragma unroll
        for (int k16 = 0; k16 < 16; k16++) {
            const int cur = k16 & 1;
            const int nxt = cur ^ 1;
            if (k16 < 15) LOADFRAGS(nxt, ab, bb, k16 + 1);
#pragma unroll
            for (int mt = 0; mt < 2; mt++)
#pragma unroll
                for (int nt = 0; nt < 4; nt++)
                    MMA16816F(acc[mt][nt], af[cur][mt],
                              &bf[cur][nt >> 1][(nt & 1) * 2]);
        }

        // fold this 128-code tile into best-2 (codes ascend per thread)
#pragma unroll
        for (int nt = 0; nt < 4; nt++) {
            int code0 = ct * 128 + wx * 32 + nt * 8 + (lane & 3) * 2;
            float w0 = swsq[code0], w1 = swsq[code0 + 1];
#pragma unroll
            for (int mt = 0; mt < 2; mt++)
#pragma unroll
                for (int g = 0; g < 2; g++) {
                    float B0 = acc[mt][nt][g * 2 + 0];
                    float B1 = acc[mt][nt][g * 2 + 1];
                    float d0 = __fadd_rn(__fsub_rn(Azr[mt][g], __fmul_rn(2.f, B0)), w0);
                    float d1 = __fadd_rn(__fsub_rn(Azr[mt][g], __fmul_rn(2.f, B1)), w1);
                    ins2(d0, code0,     b1v[mt][g], b1i[mt][g], b2v[mt][g], b2i[mt][g]);
                    ins2(d1, code0 + 1, b1v[mt][g], b1i[mt][g], b2v[mt][g], b2i[mt][g]);
                }
        }
    }

    // reduce best-2 across the 4 code-lanes (xor 1,2 stay within lane&3 group)
    float* rv1 = reinterpret_cast<float*>(smem + SM_RED);
    int*   ri1 = reinterpret_cast<int*>(smem + SM_RED + 2048);
    float* rv2 = reinterpret_cast<float*>(smem + SM_RED + 4096);
    int*   ri2 = reinterpret_cast<int*>(smem + SM_RED + 6144);
#pragma unroll
    for (int mt = 0; mt < 2; mt++)
#pragma unroll
        for (int g = 0; g < 2; g++) {
            float v1 = b1v[mt][g], v2 = b2v[mt][g];
            int   i1 = b1i[mt][g], i2 = b2i[mt][g];
#pragma unroll
            for (int m = 1; m <= 2; m <<= 1) {
                float o1v = __shfl_xor_sync(0xffffffffu, v1, m);
                int   o1i = __shfl_xor_sync(0xffffffffu, i1, m);
                float o2v = __shfl_xor_sync(0xffffffffu, v2, m);
                int   o2i = __shfl_xor_sync(0xffffffffu, i2, m);
                ins2(o1v, o1i, v1, i1, v2, i2);
                ins2(o2v, o2i, v1, i1, v2, i2);
            }
            if ((lane & 3) == 0) {
                int rl = wy * 32 + mt * 16 + (lane >> 2) + g * 8;
                rv1[rl * 4 + wx] = v1; ri1[rl * 4 + wx] = i1;
                rv2[rl * 4 + wx] = v2; ri2[rl * 4 + wx] = i2;
            }
        }
    __syncthreads();

    if (tid < ROWS_CTA) {
        float v1 = rv1[tid * 4], v2 = rv2[tid * 4];
        int   i1 = ri1[tid * 4], i2 = ri2[tid * 4];
#pragma unroll
        for (int j = 1; j < 4; j++) {
            ins2(rv1[tid * 4 + j], ri1[tid * 4 + j], v1, i1, v2, i2);
            ins2(rv2[tid * 4 + j], ri2[tid * 4 + j], v1, i1, v2, i2);
        }
        int row = row0 + tid;
        g_idx[row] = i1;
        if (!(v2 - v1 > TAU)) {
            int p = atomicAdd(&g_ambig_n, 1);
            g_ambig[p] = row;
        }
    }
}

// ---------------------------------------------------------------------------
// [4] resolver: exact fp32 rescan, 8 code-slices x 32 rows/CTA, slot loop.
// ---------------------------------------------------------------------------
__global__ void __launch_bounds__(256, 1)
resolve_kernel(const float4* __restrict__ z4, const float4* __restrict__ w4) {
    extern __shared__ float4 sm4[];
    float4* Az = sm4;                         // [RBM][D4] = 32 KB
    float4* Bw = sm4 + RBM * D4;              // [RBN][RKC4] swizzled = 64 KB
    int* rmap  = reinterpret_cast<int*>(sm4 + RBM * D4 + RBN * RKC4);

    const int cnt = g_ambig_n;
    if (cnt == 0) return;
    const int slice  = blockIdx.x & 7;
    const int worker = blockIdx.x >> 3;
    const int c0     = slice * RBN;

    const int tid = threadIdx.x;
    const int tx  = tid & 31;
    const int ty  = tid >> 5;

    for (int slot0 = worker * RBM; slot0 < cnt; slot0 += RSLOTW * RBM) {
        __syncthreads();
        if (tid < RBM) {
            int s = slot0 + tid;
            rmap[tid] = g_ambig[s < cnt ? s : cnt - 1];
        }
        __syncthreads();

        for (int i = tid; i < RBM * D4; i += 256)
            Az[i] = z4[(size_t)rmap[i >> 6] * D4 + (i & 63)];

        float Ar[RTM];
#pragma unroll
        for (int r = 0; r < RTM; r++) Ar[r] = g_zsq[rmap[ty * RTM + r]];

        unsigned long long acc[RTM][RTN];
#pragma unroll
        for (int r = 0; r < RTM; r++)
#pragma unroll
            for (int c = 0; c < RTN; c++) acc[r][c] = 0ull;

        for (int kc4 = 0; kc4 < D4; kc4 += RKC4) {
            __syncthreads();
            for (int i = tid; i < RBN * RKC4; i += 256) {
                int c = i >> 5, q = i & 31;
                Bw[c * RKC4 + (q ^ (c & 31))] = w4[(size_t)(c0 + c) * D4 + kc4 + q];
            }
            __syncthreads();

#pragma unroll 2
            for (int q = 0; q < RKC4; q++) {
                ulonglong2 a[RTM];
#pragma unroll
                for (int r = 0; r < RTM; r++)
                    a[r] = *reinterpret_cast<const ulonglong2*>(
                        &Az[(ty * RTM + r) * D4 + kc4 + q]);
#pragma unroll
                for (int c = 0; c < RTN; c++) {
                    ulonglong2 b = *reinterpret_cast<const ulonglong2*>(
                        &Bw[(c * 32 + tx) * RKC4 + (q ^ tx)]);
#pragma unroll
                    for (int r = 0; r < RTM; r++) {
                        fma2(acc[r][c], a[r].x, b.x);
                        fma2(acc[r][c], a[r].y, b.y);
                    }
                }
            }
        }

        float best[RTM];
        int   bidx[RTM];
#pragma unroll
        for (int r = 0; r < RTM; r++) { best[r] = 3.4e38f; bidx[r] = 0x7fffffff; }

#pragma unroll
        for (int c = 0; c < RTN; c++) {
            int code = c0 + c * 32 + tx;
            float wsq = g_wsq[code];
#pragma unroll
            for (int r = 0; r < RTM; r++) {
                float blo, bhi;
                unpack2(acc[r][c], blo, bhi);
                float B = __fadd_rn(blo, bhi);
                float tt = __fsub_rn(Ar[r], __fmul_rn(2.0f, B));
                float d  = __fadd_rn(tt, wsq);
                if (d < best[r]) { best[r] = d; bidx[r] = code; }
            }
        }

#pragma unroll
        for (int r = 0; r < RTM; r++) {
            float v  = best[r];
            int   id = bidx[r];
#pragma unroll
            for (int m = 16; m >= 1; m >>= 1) {
                float ov = __shfl_xor_sync(0xffffffffu, v, m);
                int   oi = __shfl_xor_sync(0xffffffffu, id, m);
                if (ov < v || (ov == v && oi < id)) { v = ov; id = oi; }
            }
            if (tx == 0 && slot0 + ty * RTM + r < cnt) {
                int row = rmap[ty * RTM + r];
                g_bestS[slice][row] = v;
                g_bidxS[slice][row] = id;
            }
        }
    }
}

// ---------------------------------------------------------------------------
// [5] merge resolver slices (ascending slice order = lowest-index tie-break)
// ---------------------------------------------------------------------------
__global__ void rmerge_kernel() {
    int i = blockIdx.x * blockDim.x + threadIdx.x;
    if (i >= g_ambig_n) return;
    int row = g_ambig[i];
    float v = g_bestS[0][row];
    int  id = g_bidxS[0][row];
#pragma unroll
    for (int s = 1; s < RSLICE; s++) {
        float ov = g_bestS[s][row];
        int   oi = g_bidxS[s][row];
        if (ov < v || (ov == v && oi < id)) { v = ov; id = oi; }
    }
    g_idx[row] = id;
}

// ---------------------------------------------------------------------------
// gather, index tail
// ---------------------------------------------------------------------------
__global__ void gather_kernel(const float* __restrict__ w, float* __restrict__ out) {
    long gid = (long)blockIdx.x * blockDim.x + threadIdx.x;
    if (gid >= (long)NPTS * D4) return;
    int row = (int)(gid >> 6);
    int col = (int)(gid & 63);
    const float4* w4 = reinterpret_cast<const float4*>(w);
    reinterpret_cast<float4*>(out)[gid] = w4[(size_t)g_idx[row] * D4 + col];
}

__global__ void idx_tail_kernel(float* __restrict__ out, int tail) {
    int i = blockIdx.x * blockDim.x + threadIdx.x;
    if (i >= tail) return;
    out[i] = (i < NPTS) ? (float)g_idx[i] : 0.0f;
}

__global__ void idx_only_kernel(float* __restrict__ out) {
    int i = blockIdx.x * blockDim.x + threadIdx.x;
    if (i < NPTS) out[i] = (float)g_idx[i];
}

// ---------------------------------------------------------------------------
extern "C" void kernel_launch(void* const* d_in, const int* in_sizes, int n_in,
                              void* d_out, int out_size) {
    const float* z = (const float*)d_in[0];
    const float* w = (const float*)d_in[1];

    reset_kernel<<<1, 1>>>();                                    // [0]
    conv_w_kernel<<<64, 256>>>(w, 0);                            // [1]
    conv_w_kernel<<<64, 256>>>(w, 512);                          // [2]

    cudaFuncSetAttribute(mma_filter_kernel,
                         cudaFuncAttributeMaxDynamicSharedMemorySize, SM_TOTAL);
    mma_filter_kernel<<<NPTS / ROWS_CTA, THR, SM_TOTAL>>>(       // [3] HOT
        reinterpret_cast<const float4*>(z));

    cudaFuncSetAttribute(resolve_kernel,
                         cudaFuncAttributeMaxDynamicSharedMemorySize, RSM_TOTAL);
    resolve_kernel<<<RSLICE * RSLOTW, 256, RSM_TOTAL>>>(         // [4]
        reinterpret_cast<const float4*>(z), reinterpret_cast<const float4*>(w));

    rmerge_kernel<<<NPTS / 256, 256>>>();                        // [5]

    const long q_elems = (long)NPTS * DIM;
    if (out_size == NPTS) {
        idx_only_kernel<<<(NPTS + 255) / 256, 256>>>((float*)d_out);
    } else {
        long n4 = q_elems / 4;
        gather_kernel<<<(int)((n4 + 255) / 256), 256>>>(w, (float*)d_out);
        long tail = (long)out_size - q_elems;
        if (tail > 0) {
            idx_tail_kernel<<<(int)((tail + 255) / 256), 256>>>(
                (float*)d_out + q_elems, (int)tail);
        }
    }
}

// round 15
// speedup vs baseline: 1.1994x; 1.1994x over previous
#include <cuda_runtime.h>
#include <cuda_fp16.h>
#include <stdint.h>

// Problem constants
#define DIM   256
#define NC    1024
#define NPTS  65536
#define D4    (DIM/4)

// ---- filter kernel geometry (R12-proven config) ----
#define ROWS_CTA 128
#define KCH      128
#define THR      512        // 16 warps: wy=wid>>2 (M: 32 rows), wx=wid&3 (N: 32 codes)
#define NSTAGE   16
#define TAU      2.5e-4f

// filter smem offsets
#define SM_WSQ   0                     // 4 KB
#define SM_ZSQ   4096                  // 512 B
#define SM_RED   4608                  // 8 KB
#define SM_A     13312                 // 128 r x 512 B (fp16 z, full K, swizzled)
#define SM_B     (SM_A + 65536)        // 4 bufs x 32 KB
#define SM_TOTAL (SM_B + 131072)       // 209920 B

// ---- resolver geometry: 8 code-slices x 32 rows/CTA, slot-stride loop ----
#define RBM    32
#define RBN    128
#define RSLICE 8
#define RSLOTW 128
#define RKC4   32
#define RTM    4
#define RTN    4
#define RSM_TOTAL (RBM * 256 * 4 + RBN * RKC4 * 16 + 256)

// Scratch (static device globals; no allocation)
__device__ int   g_idx[NPTS];
__device__ float g_wsq[NC];
__device__ float g_zsq[NPTS];
__device__ int   g_ambig_n;
__device__ int   g_ambig[NPTS];
__device__ unsigned long long g_amb_pack[NPTS];   // (bits(d)<<32)|idx, atomicMin
__device__ __align__(16) unsigned short g_wf[NC * DIM];     // fp16(w)

// ---- PTX helpers (baseline ops only; no arch-'a' features) -----------------
static __device__ __forceinline__ uint32_t smem_u32(const void* p) {
    uint32_t a;
    asm("{ .reg .u64 t; cvta.to.shared.u64 t, %1; cvt.u32.u64 %0, t; }"
        : "=r"(a) : "l"(p));
    return a;
}
#define CP16(dst, src) \
    asm volatile("cp.async.cg.shared.global [%0], [%1], 16;" :: "r"(dst), "l"(src))
#define STS128(addr, v) \
    asm volatile("st.shared.v4.b32 [%0], {%1,%2,%3,%4};" \
                 :: "r"(addr), "r"((v).x), "r"((v).y), "r"((v).z), "r"((v).w))
#define LDSM4(r, addr) \
    asm volatile("ldmatrix.sync.aligned.m8n8.x4.shared.b16 {%0,%1,%2,%3}, [%4];" \
                 : "=r"((r)[0]), "=r"((r)[1]), "=r"((r)[2]), "=r"((r)[3]) : "r"(addr))
#define MMA16816F(d, a, b) \
    asm volatile("mma.sync.aligned.m16n8k16.row.col.f32.f16.f16.f32 " \
                 "{%0,%1,%2,%3}, {%4,%5,%6,%7}, {%8,%9}, {%0,%1,%2,%3};" \
                 : "+f"((d)[0]), "+f"((d)[1]), "+f"((d)[2]), "+f"((d)[3]) \
                 : "r"((a)[0]), "r"((a)[1]), "r"((a)[2]), "r"((a)[3]), \
                   "r"((b)[0]), "r"((b)[1]))
static __device__ __forceinline__ void fma2(unsigned long long& d,
                                            unsigned long long a,
                                            unsigned long long b) {
    asm("fma.rn.f32x2 %0, %1, %2, %0;" : "+l"(d) : "l"(a), "l"(b));
}
static __device__ __forceinline__ void unpack2(unsigned long long v,
                                               float& lo, float& hi) {
    asm("mov.b64 {%0, %1}, %2;" : "=f"(lo), "=f"(hi) : "l"(v));
}

// ---------------------------------------------------------------------------
// [0] convert w -> fp16 + exact fp32 |w|^2 (+ worklist counter reset)
// ---------------------------------------------------------------------------
__global__ void conv_w_kernel(const float* __restrict__ w) {
    if (blockIdx.x == 0 && threadIdx.x == 0) g_ambig_n = 0;
    int row  = (blockIdx.x * blockDim.x + threadIdx.x) >> 5;
    int lane = threadIdx.x & 31;
    if (row >= NC) return;
    const float4* src = reinterpret_cast<const float4*>(w + (size_t)row * DIM);
    float4 a = src[lane * 2], b = src[lane * 2 + 1];
    float x[8] = {a.x, a.y, a.z, a.w, b.x, b.y, b.z, b.w};
    float s = 0.f;
    uint32_t pk[4];
#pragma unroll
    for (int j = 0; j < 4; j++) {
        s += x[2 * j] * x[2 * j] + x[2 * j + 1] * x[2 * j + 1];
        uint32_t lo = __half_as_ushort(__float2half_rn(x[2 * j]));
        uint32_t hi = __half_as_ushort(__float2half_rn(x[2 * j + 1]));
        pk[j] = lo | (hi << 16);
    }
    *reinterpret_cast<uint4*>(g_wf + (size_t)row * DIM + lane * 8) =
        make_uint4(pk[0], pk[1], pk[2], pk[3]);
#pragma unroll
    for (int t = 16; t >= 1; t >>= 1) s += __shfl_xor_sync(0xffffffffu, s, t);
    if (lane == 0) g_wsq[row] = s;
}

// ---------------------------------------------------------------------------
// B chunk stage into ring-4 buffer (it mod 4): 128 codes x 128 k fp16 (32 KB)
// ---------------------------------------------------------------------------
static __device__ __forceinline__ void stage_B(uint32_t sb, int tid, int it) {
    const int ct = it >> 1, kc = it & 1, buf = it & 3;
    const int r0 = tid >> 4, q = tid & 15;
    uint32_t dst = sb + SM_B + (uint32_t)(buf * 32768) +
                   (uint32_t)(r0 * 256 + ((q * 16) ^ ((r0 & 7) << 4)));
    const unsigned short* src =
        g_wf + (size_t)(ct * 128 + r0) * DIM + kc * KCH + q * 8;
#pragma unroll
    for (int j = 0; j < 4; j++)
        CP16(dst + j * 8192, src + j * 32 * DIM);
}

// lex insert of candidate (v,i) into best-2
static __device__ __forceinline__ void ins2(float v, int i, float& b1v, int& b1i,
                                            float& b2v, int& b2i) {
    if (v < b1v || (v == b1v && i < b1i)) { b2v = b1v; b2i = b1i; b1v = v; b1i = i; }
    else if (v < b2v || (v == b2v && i < b2i)) { b2v = v; b2i = i; }
}

// load one k16 step's fragments (GK = A k16 index 0..15, BK = B-local 0..7)
#define LOADFRAGS(SET, ABASE, BBASE, GK, BK) do {                   \
    uint32_t ak_ = ((uint32_t)((GK) * 32) + akh) ^ xl;              \
    uint32_t bk_ = ((uint32_t)((BK) * 32) + bkh) ^ xl;              \
    LDSM4(af[SET][0], (ABASE) + ak_);                               \
    LDSM4(af[SET][1], (ABASE) + 8192 + ak_);                        \
    LDSM4(bf[SET][0], (BBASE) + bk_);                               \
    LDSM4(bf[SET][1], (BBASE) + 4096 + bk_);                        \
} while (0)

// ---------------------------------------------------------------------------
// [1] HOT: single-product fp16 HMMA filter (R12 config); fused z conv + |z|^2.
// ---------------------------------------------------------------------------
__global__ void __launch_bounds__(THR, 1)
mma_filter_kernel(const float4* __restrict__ z4) {
    extern __shared__ char smem[];
    const uint32_t sb = smem_u32(smem);
    const int tid  = threadIdx.x;
    const int lane = tid & 31;
    const int wid  = tid >> 5;
    const int wx   = wid & 3;
    const int wy   = wid >> 2;
    const int row0 = blockIdx.x * ROWS_CTA;

    float* swsq = reinterpret_cast<float*>(smem + SM_WSQ);
    float* szsq = reinterpret_cast<float*>(smem + SM_ZSQ);
    for (int i = tid; i < NC; i += THR) swsq[i] = g_wsq[i];

    stage_B(sb, tid, 0);
    asm volatile("cp.async.commit_group;" ::: "memory");
    stage_B(sb, tid, 1);
    asm volatile("cp.async.commit_group;" ::: "memory");

    // convert z fp32 -> fp16 into swizzled smem A + per-row |z|^2
    {
        const int r  = tid >> 2;
        const int qq = tid & 3;
        const float4* zr = z4 + (size_t)(row0 + r) * D4 + qq * 16;
        const uint32_t abase = sb + SM_A + (uint32_t)(r * 512);
        const uint32_t sw    = (uint32_t)((r & 7) << 4);
        float s = 0.f;
#pragma unroll
        for (int j = 0; j < 8; j++) {
            float4 a = zr[2 * j], b = zr[2 * j + 1];
            float x[8] = {a.x, a.y, a.z, a.w, b.x, b.y, b.z, b.w};
            uint4 pk;
            uint32_t* pkp = &pk.x;
#pragma unroll
            for (int e = 0; e < 4; e++) {
                s += x[2 * e] * x[2 * e] + x[2 * e + 1] * x[2 * e + 1];
                uint32_t lo = __half_as_ushort(__float2half_rn(x[2 * e]));
                uint32_t hi = __half_as_ushort(__float2half_rn(x[2 * e + 1]));
                pkp[e] = lo | (hi << 16);
            }
            uint32_t off = abase + ((uint32_t)((qq * 8 + j) * 16) ^ sw);
            STS128(off, pk);
        }
        s += __shfl_xor_sync(0xffffffffu, s, 1);
        s += __shfl_xor_sync(0xffffffffu, s, 2);
        if (qq == 0) { szsq[r] = s; g_zsq[row0 + r] = s; }
    }

    float b1v[2][2], b2v[2][2];
    int   b1i[2][2], b2i[2][2];
#pragma unroll
    for (int mt = 0; mt < 2; mt++)
#pragma unroll
        for (int g = 0; g < 2; g++) {
            b1v[mt][g] = b2v[mt][g] = 3.4e38f;
            b1i[mt][g] = b2i[mt][g] = 0x7fffffff;
        }

    const uint32_t xl   = (uint32_t)((lane & 7) << 4);
    const uint32_t aRow = (uint32_t)((wy * 32 + (lane & 15)) * 512);
    const uint32_t akh  = (uint32_t)(((lane >> 4) & 1) * 16);
    const uint32_t bRow = (uint32_t)((wx * 32 + ((lane >> 4) << 3) + (lane & 7)) * 256);
    const uint32_t bkh  = (uint32_t)(((lane >> 3) & 1) * 16);

    uint32_t af[2][2][4];
    uint32_t bf[2][2][4];

    asm volatile("cp.async.wait_group 1;" ::: "memory");
    __syncthreads();

    float Azr[2][2];
#pragma unroll
    for (int mt = 0; mt < 2; mt++)
#pragma unroll
        for (int g = 0; g < 2; g++)
            Azr[mt][g] = szsq[wy * 32 + mt * 16 + (lane >> 2) + g * 8];

    LOADFRAGS(0, sb + SM_A + aRow, sb + SM_B + bRow, 0, 0);

    float acc[2][4][4];
#pragma unroll
    for (int mt = 0; mt < 2; mt++)
#pragma unroll
        for (int nt = 0; nt < 4; nt++)
#pragma unroll
            for (int e = 0; e < 4; e++) acc[mt][nt][e] = 0.f;

    for (int it = 0; it < NSTAGE; it++) {
        if (it < NSTAGE - 2) {
            stage_B(sb, tid, it + 2);
            asm volatile("cp.async.commit_group;" ::: "memory");
            asm volatile("cp.async.wait_group 1;" ::: "memory");
        } else {
            asm volatile("cp.async.wait_group 0;" ::: "memory");
        }
        __syncthreads();

        const int kc  = it & 1;
        const int kcn = (it + 1) & 1;
        const uint32_t ab  = sb + SM_A + aRow;
        const uint32_t bb  = sb + SM_B + (uint32_t)((it & 3) * 32768) + bRow;
        const uint32_t bbn = sb + SM_B + (uint32_t)(((it + 1) & 3) * 32768) + bRow;
        const bool lastit = (it == NSTAGE - 1);

#pragma unroll
        for (int k16 = 0; k16 < 8; k16++) {
            const int cur = k16 & 1;
            const int nxt = cur ^ 1;
            if (k16 < 7) {
                LOADFRAGS(nxt, ab, bb, kc * 8 + k16 + 1, k16 + 1);
            } else if (!lastit) {
                LOADFRAGS(nxt, ab, bbn, kcn * 8, 0);
            }
#pragma unroll
            for (int mt = 0; mt < 2; mt++)
#pragma unroll
                for (int nt = 0; nt < 4; nt++)
                    MMA16816F(acc[mt][nt], af[cur][mt],
                              &bf[cur][nt >> 1][(nt & 1) * 2]);
        }

        if (kc == 1) {
            const int ct = it >> 1;
#pragma unroll
            for (int nt = 0; nt < 4; nt++) {
                int code0 = ct * 128 + wx * 32 + nt * 8 + (lane & 3) * 2;
                float w0 = swsq[code0], w1 = swsq[code0 + 1];
#pragma unroll
                for (int mt = 0; mt < 2; mt++)
#pragma unroll
                    for (int g = 0; g < 2; g++) {
                        float B0 = acc[mt][nt][g * 2 + 0];
                        float B1 = acc[mt][nt][g * 2 + 1];
                        float d0 = __fadd_rn(__fsub_rn(Azr[mt][g], __fmul_rn(2.f, B0)), w0);
                        float d1 = __fadd_rn(__fsub_rn(Azr[mt][g], __fmul_rn(2.f, B1)), w1);
                        ins2(d0, code0,     b1v[mt][g], b1i[mt][g], b2v[mt][g], b2i[mt][g]);
                        ins2(d1, code0 + 1, b1v[mt][g], b1i[mt][g], b2v[mt][g], b2i[mt][g]);
                    }
            }
#pragma unroll
            for (int mt = 0; mt < 2; mt++)
#pragma unroll
                for (int nt = 0; nt < 4; nt++)
#pragma unroll
                    for (int e = 0; e < 4; e++) acc[mt][nt][e] = 0.f;
        }
    }

    // reduce best-2 across the 4 code-lanes
    float* rv1 = reinterpret_cast<float*>(smem + SM_RED);
    int*   ri1 = reinterpret_cast<int*>(smem + SM_RED + 2048);
    float* rv2 = reinterpret_cast<float*>(smem + SM_RED + 4096);
    int*   ri2 = reinterpret_cast<int*>(smem + SM_RED + 6144);
#pragma unroll
    for (int mt = 0; mt < 2; mt++)
#pragma unroll
        for (int g = 0; g < 2; g++) {
            float v1 = b1v[mt][g], v2 = b2v[mt][g];
            int   i1 = b1i[mt][g], i2 = b2i[mt][g];
#pragma unroll
            for (int m = 1; m <= 2; m <<= 1) {
                float o1v = __shfl_xor_sync(0xffffffffu, v1, m);
                int   o1i = __shfl_xor_sync(0xffffffffu, i1, m);
                float o2v = __shfl_xor_sync(0xffffffffu, v2, m);
                int   o2i = __shfl_xor_sync(0xffffffffu, i2, m);
                ins2(o1v, o1i, v1, i1, v2, i2);
                ins2(o2v, o2i, v1, i1, v2, i2);
            }
            if ((lane & 3) == 0) {
                int rl = wy * 32 + mt * 16 + (lane >> 2) + g * 8;
                rv1[rl * 4 + wx] = v1; ri1[rl * 4 + wx] = i1;
                rv2[rl * 4 + wx] = v2; ri2[rl * 4 + wx] = i2;
            }
        }
    __syncthreads();

    if (tid < ROWS_CTA) {
        float v1 = rv1[tid * 4], v2 = rv2[tid * 4];
        int   i1 = ri1[tid * 4], i2 = ri2[tid * 4];
#pragma unroll
        for (int j = 1; j < 4; j++) {
            ins2(rv1[tid * 4 + j], ri1[tid * 4 + j], v1, i1, v2, i2);
            ins2(rv2[tid * 4 + j], ri2[tid * 4 + j], v1, i1, v2, i2);
        }
        int row = row0 + tid;
        if (v2 - v1 > TAU) {
            g_idx[row] = i1;                       // certified
        } else {
            int p = atomicAdd(&g_ambig_n, 1);      // ambiguous -> exact resolve
            g_ambig[p] = row;
            g_amb_pack[p] = ~0ull;
            g_idx[row] = -(p + 1);                 // marker for gather
        }
    }
}

// ---------------------------------------------------------------------------
// [2] resolver: exact fp32 rescan; result via atomicMin on (d,idx) packing.
// pack = (bits(d)<<32) | idx; d > 0 so uint ordering == float ordering;
// min pack == lex-min (d, idx) == reference argmax(-d) semantics.
// ---------------------------------------------------------------------------
__global__ void __launch_bounds__(256, 1)
resolve_kernel(const float4* __restrict__ z4, const float4* __restrict__ w4) {
    extern __shared__ float4 sm4[];
    float4* Az = sm4;                         // [RBM][D4] = 32 KB
    float4* Bw = sm4 + RBM * D4;              // [RBN][RKC4] swizzled = 64 KB
    int* rmap  = reinterpret_cast<int*>(sm4 + RBM * D4 + RBN * RKC4);

    const int cnt = g_ambig_n;
    if (cnt == 0) return;
    const int slice  = blockIdx.x & 7;
    const int worker = blockIdx.x >> 3;
    const int c0     = slice * RBN;

    const int tid = threadIdx.x;
    const int tx  = tid & 31;
    const int ty  = tid >> 5;

    for (int slot0 = worker * RBM; slot0 < cnt; slot0 += RSLOTW * RBM) {
        __syncthreads();
        if (tid < RBM) {
            int s = slot0 + tid;
            rmap[tid] = g_ambig[s < cnt ? s : cnt - 1];
        }
        __syncthreads();

        for (int i = tid; i < RBM * D4; i += 256)
            Az[i] = z4[(size_t)rmap[i >> 6] * D4 + (i & 63)];

        float Ar[RTM];
#pragma unroll
        for (int r = 0; r < RTM; r++) Ar[r] = g_zsq[rmap[ty * RTM + r]];

        unsigned long long acc[RTM][RTN];
#pragma unroll
        for (int r = 0; r < RTM; r++)
#pragma unroll
            for (int c = 0; c < RTN; c++) acc[r][c] = 0ull;

        for (int kc4 = 0; kc4 < D4; kc4 += RKC4) {
            __syncthreads();
            for (int i = tid; i < RBN * RKC4; i += 256) {
                int c = i >> 5, q = i & 31;
                Bw[c * RKC4 + (q ^ (c & 31))] = w4[(size_t)(c0 + c) * D4 + kc4 + q];
            }
            __syncthreads();

#pragma unroll 2
            for (int q = 0; q < RKC4; q++) {
                ulonglong2 a[RTM];
#pragma unroll
                for (int r = 0; r < RTM; r++)
                    a[r] = *reinterpret_cast<const ulonglong2*>(
                        &Az[(ty * RTM + r) * D4 + kc4 + q]);
#pragma unroll
                for (int c = 0; c < RTN; c++) {
                    ulonglong2 b = *reinterpret_cast<const ulonglong2*>(
                        &Bw[(c * 32 + tx) * RKC4 + (q ^ tx)]);
#pragma unroll
                    for (int r = 0; r < RTM; r++) {
                        fma2(acc[r][c], a[r].x, b.x);
                        fma2(acc[r][c], a[r].y, b.y);
                    }
                }
            }
        }

        float best[RTM];
        int   bidx[RTM];
#pragma unroll
        for (int r = 0; r < RTM; r++) { best[r] = 3.4e38f; bidx[r] = 0x7fffffff; }

#pragma unroll
        for (int c = 0; c < RTN; c++) {
            int code = c0 + c * 32 + tx;
            float wsq = g_wsq[code];
#pragma unroll
            for (int r = 0; r < RTM; r++) {
                float blo, bhi;
                unpack2(acc[r][c], blo, bhi);
                float B = __fadd_rn(blo, bhi);
                float tt = __fsub_rn(Ar[r], __fmul_rn(2.0f, B));
                float d  = __fadd_rn(tt, wsq);
                if (d < best[r]) { best[r] = d; bidx[r] = code; }
            }
        }

#pragma unroll
        for (int r = 0; r < RTM; r++) {
            float v  = best[r];
            int   id = bidx[r];
#pragma unroll
            for (int m = 16; m >= 1; m >>= 1) {
                float ov = __shfl_xor_sync(0xffffffffu, v, m);
                int   oi = __shfl_xor_sync(0xffffffffu, id, m);
                if (ov < v || (ov == v && oi < id)) { v = ov; id = oi; }
            }
            int slot = slot0 + ty * RTM + r;
            if (tx == 0 && slot < cnt) {
                unsigned long long pk =
                    ((unsigned long long)__float_as_uint(v) << 32) | (unsigned)id;
                atomicMin(&g_amb_pack[slot], pk);
            }
        }
    }
}

// ---------------------------------------------------------------------------
// [3] gather + index tail (single kernel). Ambiguous rows decode g_amb_pack.
// ---------------------------------------------------------------------------
static __device__ __forceinline__ int resolved_idx(int row) {
    int idx = g_idx[row];
    if (idx < 0) idx = (int)(g_amb_pack[-idx - 1] & 0xffffffffu);
    return idx;
}

__global__ void gather_kernel(const float* __restrict__ w, float* __restrict__ out,
                              long n4, long total) {
    long gid = (long)blockIdx.x * blockDim.x + threadIdx.x;
    if (gid < n4) {
        int row = (int)(gid >> 6);
        int col = (int)(gid & 63);
        const float4* w4 = reinterpret_cast<const float4*>(w);
        reinterpret_cast<float4*>(out)[gid] =
            w4[(size_t)resolved_idx(row) * D4 + col];
    } else if (gid < total) {
        long i = gid - n4;                 // tail element (float), i-th index
        out[n4 * 4 + i] = (i < NPTS) ? (float)resolved_idx((int)i) : 0.0f;
    }
}

__global__ void idx_only_kernel(float* __restrict__ out) {
    int i = blockIdx.x * blockDim.x + threadIdx.x;
    if (i < NPTS) out[i] = (float)resolved_idx(i);
}

// ---------------------------------------------------------------------------
extern "C" void kernel_launch(void* const* d_in, const int* in_sizes, int n_in,
                              void* d_out, int out_size) {
    const float* z = (const float*)d_in[0];
    const float* w = (const float*)d_in[1];

    conv_w_kernel<<<128, 256>>>(w);                              // [0] (+reset)

    cudaFuncSetAttribute(mma_filter_kernel,
                         cudaFuncAttributeMaxDynamicSharedMemorySize, SM_TOTAL);
    mma_filter_kernel<<<NPTS / ROWS_CTA, THR, SM_TOTAL>>>(       // [1] HOT
        reinterpret_cast<const float4*>(z));

    cudaFuncSetAttribute(resolve_kernel,
                         cudaFuncAttributeMaxDynamicSharedMemorySize, RSM_TOTAL);
    resolve_kernel<<<RSLICE * RSLOTW, 256, RSM_TOTAL>>>(         // [2]
        reinterpret_cast<const float4*>(z), reinterpret_cast<const float4*>(w));

    const long q_elems = (long)NPTS * DIM;
    if (out_size == NPTS) {
        idx_only_kernel<<<(NPTS + 255) / 256, 256>>>((float*)d_out);
    } else {
        long n4    = q_elems / 4;
        long tail  = (long)out_size - q_elems;
        long total = n4 + (tail > 0 ? tail : 0);
        gather_kernel<<<(int)((total + 255) / 256), 256>>>(      // [3]
            w, (float*)d_out, n4, total);
    }
}

// round 16
// speedup vs baseline: 1.3614x; 1.1351x over previous
#include <cuda_runtime.h>
#include <cuda_fp16.h>
#include <stdint.h>

// Problem constants
#define DIM   256
#define NC    1024
#define NPTS  65536
#define D4    (DIM/4)

// ---- filter kernel geometry: 2 CTAs/SM ----
#define ROWS_CTA 64
#define KCH      64
#define THR      256        // 8 warps: wy=wid>>2 (M: 32 rows x2), wx=wid&3 (N: 32 codes)
#define NSTAGE   32         // 8 code tiles x 4 k-chunks
#define TAU      2.5e-4f

// filter smem offsets (total 107520 B -> 2 CTAs/SM)
#define SM_WSQ   0                     // 4 KB
#define SM_ZSQ   4096                  // 256 B (64 f32)
#define SM_RED   4608                  // 4 KB: rv1,ri1,rv2,ri2 [64][4]
#define SM_A     9216                  // 64 r x 512 B (fp16 z, full K, swizzled) = 32 KB
#define SM_B     (SM_A + 32768)        // 4 bufs x 16 KB (128 codes x 64 k fp16)
#define SM_TOTAL (SM_B + 65536)        // 107520 B

// ---- resolver geometry: 8 code-slices x 32 rows/CTA, slot-stride loop ----
#define RBM    32
#define RBN    128
#define RSLICE 8
#define RSLOTW 128
#define RKC4   32
#define RTM    4
#define RTN    4
#define RSM_TOTAL (RBM * 256 * 4 + RBN * RKC4 * 16 + 256)

// Scratch (static device globals; no allocation)
__device__ int   g_idx[NPTS];
__device__ float g_wsq[NC];
__device__ float g_zsq[NPTS];
__device__ int   g_ambig_n;
__device__ int   g_ambig[NPTS];
__device__ unsigned long long g_amb_pack[NPTS];   // (bits(d)<<32)|idx, atomicMin
__device__ __align__(16) unsigned short g_wf[NC * DIM];     // fp16(w)

// ---- PTX helpers (baseline ops only; no arch-'a' features) -----------------
static __device__ __forceinline__ uint32_t smem_u32(const void* p) {
    uint32_t a;
    asm("{ .reg .u64 t; cvta.to.shared.u64 t, %1; cvt.u32.u64 %0, t; }"
        : "=r"(a) : "l"(p));
    return a;
}
#define CP16(dst, src) \
    asm volatile("cp.async.cg.shared.global [%0], [%1], 16;" :: "r"(dst), "l"(src))
#define STS128(addr, v) \
    asm volatile("st.shared.v4.b32 [%0], {%1,%2,%3,%4};" \
                 :: "r"(addr), "r"((v).x), "r"((v).y), "r"((v).z), "r"((v).w))
#define LDSM4(r, addr) \
    asm volatile("ldmatrix.sync.aligned.m8n8.x4.shared.b16 {%0,%1,%2,%3}, [%4];" \
                 : "=r"((r)[0]), "=r"((r)[1]), "=r"((r)[2]), "=r"((r)[3]) : "r"(addr))
#define MMA16816F(d, a, b) \
    asm volatile("mma.sync.aligned.m16n8k16.row.col.f32.f16.f16.f32 " \
                 "{%0,%1,%2,%3}, {%4,%5,%6,%7}, {%8,%9}, {%0,%1,%2,%3};" \
                 : "+f"((d)[0]), "+f"((d)[1]), "+f"((d)[2]), "+f"((d)[3]) \
                 : "r"((a)[0]), "r"((a)[1]), "r"((a)[2]), "r"((a)[3]), \
                   "r"((b)[0]), "r"((b)[1]))
static __device__ __forceinline__ void fma2(unsigned long long& d,
                                            unsigned long long a,
                                            unsigned long long b) {
    asm("fma.rn.f32x2 %0, %1, %2, %0;" : "+l"(d) : "l"(a), "l"(b));
}
static __device__ __forceinline__ void unpack2(unsigned long long v,
                                               float& lo, float& hi) {
    asm("mov.b64 {%0, %1}, %2;" : "=f"(lo), "=f"(hi) : "l"(v));
}

// ---------------------------------------------------------------------------
// [0] convert w -> fp16 + exact fp32 |w|^2 (+ worklist counter reset)
// ---------------------------------------------------------------------------
__global__ void conv_w_kernel(const float* __restrict__ w) {
    if (blockIdx.x == 0 && threadIdx.x == 0) g_ambig_n = 0;
    int row  = (blockIdx.x * blockDim.x + threadIdx.x) >> 5;
    int lane = threadIdx.x & 31;
    if (row >= NC) return;
    const float4* src = reinterpret_cast<const float4*>(w + (size_t)row * DIM);
    float4 a = src[lane * 2], b = src[lane * 2 + 1];
    float x[8] = {a.x, a.y, a.z, a.w, b.x, b.y, b.z, b.w};
    float s = 0.f;
    uint32_t pk[4];
#pragma unroll
    for (int j = 0; j < 4; j++) {
        s += x[2 * j] * x[2 * j] + x[2 * j + 1] * x[2 * j + 1];
        uint32_t lo = __half_as_ushort(__float2half_rn(x[2 * j]));
        uint32_t hi = __half_as_ushort(__float2half_rn(x[2 * j + 1]));
        pk[j] = lo | (hi << 16);
    }
    *reinterpret_cast<uint4*>(g_wf + (size_t)row * DIM + lane * 8) =
        make_uint4(pk[0], pk[1], pk[2], pk[3]);
#pragma unroll
    for (int t = 16; t >= 1; t >>= 1) s += __shfl_xor_sync(0xffffffffu, s, t);
    if (lane == 0) g_wsq[row] = s;
}

// ---------------------------------------------------------------------------
// B chunk stage into ring-4 buffer (it mod 4): 128 codes x 64 k fp16 (16 KB).
// Rows are 128 B; swizzle (q*16)^((r&7)<<4), q in [0,8).
// ---------------------------------------------------------------------------
static __device__ __forceinline__ void stage_B(uint32_t sb, int tid, int it) {
    const int ct = it >> 2, kc = it & 3, buf = it & 3;
    const int r0 = tid >> 3, q = tid & 7;               // 32 rows per pass
    uint32_t dst = sb + SM_B + (uint32_t)(buf * 16384) +
                   (uint32_t)(r0 * 128 + ((q * 16) ^ ((r0 & 7) << 4)));
    const unsigned short* src =
        g_wf + (size_t)(ct * 128 + r0) * DIM + kc * KCH + q * 8;
#pragma unroll
    for (int j = 0; j < 4; j++)                          // rows r0 + 32j
        CP16(dst + j * 4096, src + (size_t)j * 32 * DIM);
}

// lex insert of candidate (v,i) into best-2
static __device__ __forceinline__ void ins2(float v, int i, float& b1v, int& b1i,
                                            float& b2v, int& b2i) {
    if (v < b1v || (v == b1v && i < b1i)) { b2v = b1v; b2i = b1i; b1v = v; b1i = i; }
    else if (v < b2v || (v == b2v && i < b2i)) { b2v = v; b2i = i; }
}

// load one k16 step's fragments (GK = A k16 index 0..15, BK = B-local 0..3)
// A rows 512 B (mt step 16 rows = 8192); B rows 128 B (pr step 16 rows = 2048)
#define LOADFRAGS(SET, ABASE, BBASE, GK, BK) do {                   \
    uint32_t ak_ = ((uint32_t)((GK) * 32) + akh) ^ xl;              \
    uint32_t bk_ = ((uint32_t)((BK) * 32) + bkh) ^ xl;              \
    LDSM4(af[SET][0], (ABASE) + ak_);                               \
    LDSM4(af[SET][1], (ABASE) + 8192 + ak_);                        \
    LDSM4(bf[SET][0], (BBASE) + bk_);                               \
    LDSM4(bf[SET][1], (BBASE) + 2048 + bk_);                        \
} while (0)

// ---------------------------------------------------------------------------
// [1] HOT: single-product fp16 HMMA filter; fused z conv + |z|^2.
// 256 threads, 8 warps (2 M x 4 N), 64 rows x 1024 codes per CTA, 2 CTAs/SM.
// ---------------------------------------------------------------------------
__global__ void __launch_bounds__(THR, 2)
mma_filter_kernel(const float4* __restrict__ z4) {
    extern __shared__ char smem[];
    const uint32_t sb = smem_u32(smem);
    const int tid  = threadIdx.x;
    const int lane = tid & 31;
    const int wid  = tid >> 5;
    const int wx   = wid & 3;        // N warp (32 codes)
    const int wy   = wid >> 2;       // M warp (32 rows), 0..1
    const int row0 = blockIdx.x * ROWS_CTA;

    float* swsq = reinterpret_cast<float*>(smem + SM_WSQ);
    float* szsq = reinterpret_cast<float*>(smem + SM_ZSQ);
    for (int i = tid; i < NC; i += THR) swsq[i] = g_wsq[i];

    stage_B(sb, tid, 0);
    asm volatile("cp.async.commit_group;" ::: "memory");
    stage_B(sb, tid, 1);
    asm volatile("cp.async.commit_group;" ::: "memory");

    // convert z fp32 -> fp16 into swizzled smem A + per-row |z|^2
    {
        const int r  = tid >> 2;          // row 0..63
        const int qq = tid & 3;           // quarter (64 floats)
        const float4* zr = z4 + (size_t)(row0 + r) * D4 + qq * 16;
        const uint32_t abase = sb + SM_A + (uint32_t)(r * 512);
        const uint32_t sw    = (uint32_t)((r & 7) << 4);
        float s = 0.f;
#pragma unroll
        for (int j = 0; j < 8; j++) {
            float4 a = zr[2 * j], b = zr[2 * j + 1];
            float x[8] = {a.x, a.y, a.z, a.w, b.x, b.y, b.z, b.w};
            uint4 pk;
            uint32_t* pkp = &pk.x;
#pragma unroll
            for (int e = 0; e < 4; e++) {
                s += x[2 * e] * x[2 * e] + x[2 * e + 1] * x[2 * e + 1];
                uint32_t lo = __half_as_ushort(__float2half_rn(x[2 * e]));
                uint32_t hi = __half_as_ushort(__float2half_rn(x[2 * e + 1]));
                pkp[e] = lo | (hi << 16);
            }
            uint32_t off = abase + ((uint32_t)((qq * 8 + j) * 16) ^ sw);
            STS128(off, pk);
        }
        s += __shfl_xor_sync(0xffffffffu, s, 1);
        s += __shfl_xor_sync(0xffffffffu, s, 2);
        if (qq == 0) { szsq[r] = s; g_zsq[row0 + r] = s; }
    }

    float b1v[2][2], b2v[2][2];
    int   b1i[2][2], b2i[2][2];
#pragma unroll
    for (int mt = 0; mt < 2; mt++)
#pragma unroll
        for (int g = 0; g < 2; g++) {
            b1v[mt][g] = b2v[mt][g] = 3.4e38f;
            b1i[mt][g] = b2i[mt][g] = 0x7fffffff;
        }

    const uint32_t xl   = (uint32_t)((lane & 7) << 4);
    const uint32_t aRow = (uint32_t)((wy * 32 + (lane & 15)) * 512);
    const uint32_t akh  = (uint32_t)(((lane >> 4) & 1) * 16);
    const uint32_t bRow = (uint32_t)((wx * 32 + ((lane >> 4) << 3) + (lane & 7)) * 128);
    const uint32_t bkh  = (uint32_t)(((lane >> 3) & 1) * 16);

    uint32_t af[2][2][4];   // [set][mt][4]
    uint32_t bf[2][2][4];   // [set][pr][4]

    asm volatile("cp.async.wait_group 1;" ::: "memory");
    __syncthreads();

    float Azr[2][2];
#pragma unroll
    for (int mt = 0; mt < 2; mt++)
#pragma unroll
        for (int g = 0; g < 2; g++)
            Azr[mt][g] = szsq[wy * 32 + mt * 16 + (lane >> 2) + g * 8];

    LOADFRAGS(0, sb + SM_A + aRow, sb + SM_B + bRow, 0, 0);

    float acc[2][4][4];
#pragma unroll
    for (int mt = 0; mt < 2; mt++)
#pragma unroll
        for (int nt = 0; nt < 4; nt++)
#pragma unroll
            for (int e = 0; e < 4; e++) acc[mt][nt][e] = 0.f;

    for (int it = 0; it < NSTAGE; it++) {
        if (it < NSTAGE - 2) {
            stage_B(sb, tid, it + 2);
            asm volatile("cp.async.commit_group;" ::: "memory");
            asm volatile("cp.async.wait_group 1;" ::: "memory");
        } else {
            asm volatile("cp.async.wait_group 0;" ::: "memory");
        }
        __syncthreads();   // bufs it and it+1 fully valid for all threads

        const int kc  = it & 3;
        const int kcn = (it + 1) & 3;
        const uint32_t ab  = sb + SM_A + aRow;
        const uint32_t bb  = sb + SM_B + (uint32_t)((it & 3) * 16384) + bRow;
        const uint32_t bbn = sb + SM_B + (uint32_t)(((it + 1) & 3) * 16384) + bRow;
        const bool lastit = (it == NSTAGE - 1);

#pragma unroll
        for (int k16 = 0; k16 < 4; k16++) {
            const int cur = k16 & 1;
            const int nxt = cur ^ 1;
            if (k16 < 3) {
                LOADFRAGS(nxt, ab, bb, kc * 4 + k16 + 1, k16 + 1);
            } else if (!lastit) {
                LOADFRAGS(nxt, ab, bbn, kcn * 4, 0);
            }
#pragma unroll
            for (int mt = 0; mt < 2; mt++)
#pragma unroll
                for (int nt = 0; nt < 4; nt++)
                    MMA16816F(acc[mt][nt], af[cur][mt],
                              &bf[cur][nt >> 1][(nt & 1) * 2]);
        }

        if (kc == 3) {
            // ct complete: fold 128-code tile into best-2 (codes ascend)
            const int ct = it >> 2;
#pragma unroll
            for (int nt = 0; nt < 4; nt++) {
                int code0 = ct * 128 + wx * 32 + nt * 8 + (lane & 3) * 2;
                float w0 = swsq[code0], w1 = swsq[code0 + 1];
#pragma unroll
                for (int mt = 0; mt < 2; mt++)
#pragma unroll
                    for (int g = 0; g < 2; g++) {
                        float B0 = acc[mt][nt][g * 2 + 0];
                        float B1 = acc[mt][nt][g * 2 + 1];
                        float d0 = __fadd_rn(__fsub_rn(Azr[mt][g], __fmul_rn(2.f, B0)), w0);
                        float d1 = __fadd_rn(__fsub_rn(Azr[mt][g], __fmul_rn(2.f, B1)), w1);
                        ins2(d0, code0,     b1v[mt][g], b1i[mt][g], b2v[mt][g], b2i[mt][g]);
                        ins2(d1, code0 + 1, b1v[mt][g], b1i[mt][g], b2v[mt][g], b2i[mt][g]);
                    }
            }
#pragma unroll
            for (int mt = 0; mt < 2; mt++)
#pragma unroll
                for (int nt = 0; nt < 4; nt++)
#pragma unroll
                    for (int e = 0; e < 4; e++) acc[mt][nt][e] = 0.f;
        }
    }

    // reduce best-2 across the 4 code-lanes (xor 1,2 stay within lane&3 group)
    float* rv1 = reinterpret_cast<float*>(smem + SM_RED);
    int*   ri1 = reinterpret_cast<int*>(smem + SM_RED + 1024);
    float* rv2 = reinterpret_cast<float*>(smem + SM_RED + 2048);
    int*   ri2 = reinterpret_cast<int*>(smem + SM_RED + 3072);
#pragma unroll
    for (int mt = 0; mt < 2; mt++)
#pragma unroll
        for (int g = 0; g < 2; g++) {
            float v1 = b1v[mt][g], v2 = b2v[mt][g];
            int   i1 = b1i[mt][g], i2 = b2i[mt][g];
#pragma unroll
            for (int m = 1; m <= 2; m <<= 1) {
                float o1v = __shfl_xor_sync(0xffffffffu, v1, m);
                int   o1i = __shfl_xor_sync(0xffffffffu, i1, m);
                float o2v = __shfl_xor_sync(0xffffffffu, v2, m);
                int   o2i = __shfl_xor_sync(0xffffffffu, i2, m);
                ins2(o1v, o1i, v1, i1, v2, i2);
                ins2(o2v, o2i, v1, i1, v2, i2);
            }
            if ((lane & 3) == 0) {
                int rl = wy * 32 + mt * 16 + (lane >> 2) + g * 8;
                rv1[rl * 4 + wx] = v1; ri1[rl * 4 + wx] = i1;
                rv2[rl * 4 + wx] = v2; ri2[rl * 4 + wx] = i2;
            }
        }
    __syncthreads();

    if (tid < ROWS_CTA) {
        float v1 = rv1[tid * 4], v2 = rv2[tid * 4];
        int   i1 = ri1[tid * 4], i2 = ri2[tid * 4];
#pragma unroll
        for (int j = 1; j < 4; j++) {
            ins2(rv1[tid * 4 + j], ri1[tid * 4 + j], v1, i1, v2, i2);
            ins2(rv2[tid * 4 + j], ri2[tid * 4 + j], v1, i1, v2, i2);
        }
        int row = row0 + tid;
        if (v2 - v1 > TAU) {
            g_idx[row] = i1;                       // certified
        } else {
            int p = atomicAdd(&g_ambig_n, 1);      // ambiguous -> exact resolve
            g_ambig[p] = row;
            g_amb_pack[p] = ~0ull;
            g_idx[row] = -(p + 1);                 // marker for gather
        }
    }
}

// ---------------------------------------------------------------------------
// [2] resolver: exact fp32 rescan; result via atomicMin on (d,idx) packing.
// pack = (bits(d)<<32) | idx; d > 0 so uint ordering == float ordering.
// ---------------------------------------------------------------------------
__global__ void __launch_bounds__(256, 1)
resolve_kernel(const float4* __restrict__ z4, const float4* __restrict__ w4) {
    extern __shared__ float4 sm4[];
    float4* Az = sm4;                         // [RBM][D4] = 32 KB
    float4* Bw = sm4 + RBM * D4;              // [RBN][RKC4] swizzled = 64 KB
    int* rmap  = reinterpret_cast<int*>(sm4 + RBM * D4 + RBN * RKC4);

    const int cnt = g_ambig_n;
    if (cnt == 0) return;
    const int slice  = blockIdx.x & 7;
    const int worker = blockIdx.x >> 3;
    const int c0     = slice * RBN;

    const int tid = threadIdx.x;
    const int tx  = tid & 31;
    const int ty  = tid >> 5;

    for (int slot0 = worker * RBM; slot0 < cnt; slot0 += RSLOTW * RBM) {
        __syncthreads();
        if (tid < RBM) {
            int s = slot0 + tid;
            rmap[tid] = g_ambig[s < cnt ? s : cnt - 1];
        }
        __syncthreads();

        for (int i = tid; i < RBM * D4; i += 256)
            Az[i] = z4[(size_t)rmap[i >> 6] * D4 + (i & 63)];

        float Ar[RTM];
#pragma unroll
        for (int r = 0; r < RTM; r++) Ar[r] = g_zsq[rmap[ty * RTM + r]];

        unsigned long long acc[RTM][RTN];
#pragma unroll
        for (int r = 0; r < RTM; r++)
#pragma unroll
            for (int c = 0; c < RTN; c++) acc[r][c] = 0ull;

        for (int kc4 = 0; kc4 < D4; kc4 += RKC4) {
            __syncthreads();
            for (int i = tid; i < RBN * RKC4; i += 256) {
                int c = i >> 5, q = i & 31;
                Bw[c * RKC4 + (q ^ (c & 31))] = w4[(size_t)(c0 + c) * D4 + kc4 + q];
            }
            __syncthreads();

#pragma unroll 2
            for (int q = 0; q < RKC4; q++) {
                ulonglong2 a[RTM];
#pragma unroll
                for (int r = 0; r < RTM; r++)
                    a[r] = *reinterpret_cast<const ulonglong2*>(
                        &Az[(ty * RTM + r) * D4 + kc4 + q]);
#pragma unroll
                for (int c = 0; c < RTN; c++) {
                    ulonglong2 b = *reinterpret_cast<const ulonglong2*>(
                        &Bw[(c * 32 + tx) * RKC4 + (q ^ tx)]);
#pragma unroll
                    for (int r = 0; r < RTM; r++) {
                        fma2(acc[r][c], a[r].x, b.x);
                        fma2(acc[r][c], a[r].y, b.y);
                    }
                }
            }
        }

        float best[RTM];
        int   bidx[RTM];
#pragma unroll
        for (int r = 0; r < RTM; r++) { best[r] = 3.4e38f; bidx[r] = 0x7fffffff; }

#pragma unroll
        for (int c = 0; c < RTN; c++) {
            int code = c0 + c * 32 + tx;
            float wsq = g_wsq[code];
#pragma unroll
            for (int r = 0; r < RTM; r++) {
                float blo, bhi;
                unpack2(acc[r][c], blo, bhi);
                float B = __fadd_rn(blo, bhi);
                float tt = __fsub_rn(Ar[r], __fmul_rn(2.0f, B));
                float d  = __fadd_rn(tt, wsq);
                if (d < best[r]) { best[r] = d; bidx[r] = code; }
            }
        }

#pragma unroll
        for (int r = 0; r < RTM; r++) {
            float v  = best[r];
            int   id = bidx[r];
#pragma unroll
            for (int m = 16; m >= 1; m >>= 1) {
                float ov = __shfl_xor_sync(0xffffffffu, v, m);
                int   oi = __shfl_xor_sync(0xffffffffu, id, m);
                if (ov < v || (ov == v && oi < id)) { v = ov; id = oi; }
            }
            int slot = slot0 + ty * RTM + r;
            if (tx == 0 && slot < cnt) {
                unsigned long long pk =
                    ((unsigned long long)__float_as_uint(v) << 32) | (unsigned)id;
                atomicMin(&g_amb_pack[slot], pk);
            }
        }
    }
}

// ---------------------------------------------------------------------------
// [3] gather + index tail (single kernel). Ambiguous rows decode g_amb_pack.
// ---------------------------------------------------------------------------
static __device__ __forceinline__ int resolved_idx(int row) {
    int idx = g_idx[row];
    if (idx < 0) idx = (int)(g_amb_pack[-idx - 1] & 0xffffffffu);
    return idx;
}

__global__ void gather_kernel(const float* __restrict__ w, float* __restrict__ out,
                              long n4, long total) {
    long gid = (long)blockIdx.x * blockDim.x + threadIdx.x;
    if (gid < n4) {
        int row = (int)(gid >> 6);
        int col = (int)(gid & 63);
        const float4* w4 = reinterpret_cast<const float4*>(w);
        reinterpret_cast<float4*>(out)[gid] =
            w4[(size_t)resolved_idx(row) * D4 + col];
    } else if (gid < total) {
        long i = gid - n4;
        out[n4 * 4 + i] = (i < NPTS) ? (float)resolved_idx((int)i) : 0.0f;
    }
}

__global__ void idx_only_kernel(float* __restrict__ out) {
    int i = blockIdx.x * blockDim.x + threadIdx.x;
    if (i < NPTS) out[i] = (float)resolved_idx(i);
}

// ---------------------------------------------------------------------------
extern "C" void kernel_launch(void* const* d_in, const int* in_sizes, int n_in,
                              void* d_out, int out_size) {
    const float* z = (const float*)d_in[0];
    const float* w = (const float*)d_in[1];

    conv_w_kernel<<<128, 256>>>(w);                              // [0] (+reset)

    cudaFuncSetAttribute(mma_filter_kernel,
                         cudaFuncAttributeMaxDynamicSharedMemorySize, SM_TOTAL);
    mma_filter_kernel<<<NPTS / ROWS_CTA, THR, SM_TOTAL>>>(       // [1] HOT
        reinterpret_cast<const float4*>(z));

    cudaFuncSetAttribute(resolve_kernel,
                         cudaFuncAttributeMaxDynamicSharedMemorySize, RSM_TOTAL);
    resolve_kernel<<<RSLICE * RSLOTW, 256, RSM_TOTAL>>>(         // [2]
        reinterpret_cast<const float4*>(z), reinterpret_cast<const float4*>(w));

    const long q_elems = (long)NPTS * DIM;
    if (out_size == NPTS) {
        idx_only_kernel<<<(NPTS + 255) / 256, 256>>>((float*)d_out);
    } else {
        long n4    = q_elems / 4;
        long tail  = (long)out_size - q_elems;
        long total = n4 + (tail > 0 ? tail : 0);
        gather_kernel<<<(int)((total + 255) / 256), 256>>>(      // [3]
            w, (float*)d_out, n4, total);
    }
}